// round 15
// baseline (speedup 1.0000x reference)
#include <cuda_runtime.h>
#include <cuda_fp16.h>
#include <cstdint>

#define N_NODES 8192
#define F_DIM 128
#define ALPHA 0.3f
#define MAXDEG 512

// ---- device scratch ----
__device__ float    g_v[4 * F_DIM];
__device__ float    g_Sx[F_DIM];
__device__ float4   g_e1[N_NODES];   // (e^sa1_h0, e^.3sa1_h0, e^sa1_h1, e^.3sa1_h1)
__device__ float4   g_e2[N_NODES];   // (e^sa2_h0, e^.3sa2_h0, e^sa2_h1, e^.3sa2_h1)
// G as fp16, k-pair packed: [row][128 kpairs] (256 k per row)
__device__ uint32_t g_Ga[(size_t)N_NODES * 128];
// K as fp16, transposed + k-pair packed: [n(128)][128 kpairs]
__device__ uint32_t g_Kb[128 * 128];

__device__ __forceinline__ uint32_t smem_u32(const void* p) {
    uint32_t a;
    asm("{ .reg .u64 t; cvta.to.shared.u64 t, %1; cvt.u32.u64 %0, t; }" : "=r"(a) : "l"(p));
    return a;
}

// ============================================================
// Kernel 1: blocks 0..127 pack K (fp16); block 128 computes v + zeroes Sx
// ============================================================
__global__ void prep_all(const float* __restrict__ Wmap,
                         const float* __restrict__ a1w,
                         const float* __restrict__ a2w,
                         const float* __restrict__ Kw) {
    int t = threadIdx.x;
    if (blockIdx.x < 128) {
        if (t < 128) {
            int n = blockIdx.x;
            int kp = t;
            float v0 = Kw[(size_t)(2 * kp) * 128 + n];
            float v1 = Kw[(size_t)(2 * kp + 1) * 128 + n];
            __half2 h = __floats2half2_rn(v0, v1);
            g_Kb[n * 128 + kp] = *reinterpret_cast<uint32_t*>(&h);
        }
    } else {
        int h = t >> 7, f = t & 127;
        const float* wrow = Wmap + (size_t)(h * F_DIM + f) * 128;
        float s1 = 0.f, s2 = 0.f;
        for (int d = 0; d < 128; ++d) {
            float w = wrow[d];
            s1 = fmaf(w, a1w[h * 128 + d], s1);
            s2 = fmaf(w, a2w[h * 128 + d], s2);
        }
        g_v[h * F_DIM + f] = s1;
        g_v[2 * F_DIM + h * F_DIM + f] = s2;
        if (t < F_DIM) g_Sx[t] = 0.f;
    }
}

// ============================================================
// Kernel 2: per-node scores -> exponential forms + fused column sums
// ============================================================
__global__ void __launch_bounds__(256) score_kernel(const float* __restrict__ x,
                                                    const float* __restrict__ a1b,
                                                    const float* __restrict__ a2b) {
    __shared__ float sv[4 * 128];
    __shared__ float s_colp[8][128];
    int tid = threadIdx.x;
    sv[tid] = g_v[tid];
    sv[256 + tid] = g_v[256 + tid];

    int warp = tid >> 5, lane = tid & 31;
    int n = blockIdx.x * 8 + warp;
    const float* xr = x + (size_t)n * F_DIM;
    float x0 = xr[lane], x1 = xr[lane + 32], x2 = xr[lane + 64], x3 = xr[lane + 96];

    s_colp[warp][lane]      = x0;
    s_colp[warp][lane + 32] = x1;
    s_colp[warp][lane + 64] = x2;
    s_colp[warp][lane + 96] = x3;
    __syncthreads();

    float s[4];
    #pragma unroll
    for (int q = 0; q < 4; ++q) {
        const float* v = sv + q * 128;
        float acc = x0 * v[lane] + x1 * v[lane + 32] + x2 * v[lane + 64] + x3 * v[lane + 96];
        #pragma unroll
        for (int o = 16; o > 0; o >>= 1)
            acc += __shfl_down_sync(0xffffffffu, acc, o);
        s[q] = acc;
    }
    if (lane == 0) {
        float sa1_0 = s[0] + a1b[0];
        float sa1_1 = s[1] + a1b[1];
        float sa2_0 = s[2] + a2b[0];
        float sa2_1 = s[3] + a2b[1];
        g_e1[n] = make_float4(__expf(sa1_0), __expf(ALPHA * sa1_0),
                              __expf(sa1_1), __expf(ALPHA * sa1_1));
        g_e2[n] = make_float4(__expf(sa2_0), __expf(ALPHA * sa2_0),
                              __expf(sa2_1), __expf(ALPHA * sa2_1));
    }
    if (tid < 128) {
        float cs = 0.f;
        #pragma unroll
        for (int w = 0; w < 8; ++w) cs += s_colp[w][tid];
        atomicAdd(&g_Sx[tid], cs);
    }
}

// ============================================================
// Kernel 3 (main): 512 threads/row — 16 gather slots (half the
// per-warp latency chain of the 8-slot version at equal occupancy).
//   e_j = max(E1*E2_j, E1a*E2a_j) - 1  ( = exp(leaky(sa1+sa2)) - 1 )
//   g = (1/Z) * ( sum_j e_j x_j + Sx ),  Z = sum_j e_j + N
// ============================================================
__global__ void __launch_bounds__(512) gat_main(const float* __restrict__ adj,
                                                const float* __restrict__ x) {
    __shared__ int   s_list[MAXDEG];
    __shared__ float s_p0[16][132], s_p1[16][132];
    __shared__ float s_z[32];
    __shared__ int   s_cnt;

    int tid = threadIdx.x;
    int i = blockIdx.x;
    if (tid == 0) s_cnt = 0;
    __syncthreads();

    // ---- phase 1: streaming scan; 4 uint4/thread (MLP=4), OR fast path ----
    const uint4* arow = reinterpret_cast<const uint4*>(adj + (size_t)i * N_NODES);
    {
        uint4 a[4];
        #pragma unroll
        for (int it = 0; it < 4; ++it)
            a[it] = __ldcs(&arow[it * 512 + tid]);
        uint32_t any = (a[0].x | a[0].y | a[0].z | a[0].w)
                     | (a[1].x | a[1].y | a[1].z | a[1].w)
                     | (a[2].x | a[2].y | a[2].z | a[2].w)
                     | (a[3].x | a[3].y | a[3].z | a[3].w);
        if (any != 0u) {
            #pragma unroll
            for (int it = 0; it < 4; ++it) {
                uint4 v = a[it];
                if ((v.x | v.y | v.z | v.w) != 0u) {
                    int jb = (it * 512 + tid) << 2;
                    if (v.x) { int p = atomicAdd(&s_cnt, 1); if (p < MAXDEG) s_list[p] = jb; }
                    if (v.y) { int p = atomicAdd(&s_cnt, 1); if (p < MAXDEG) s_list[p] = jb + 1; }
                    if (v.z) { int p = atomicAdd(&s_cnt, 1); if (p < MAXDEG) s_list[p] = jb + 2; }
                    if (v.w) { int p = atomicAdd(&s_cnt, 1); if (p < MAXDEG) s_list[p] = jb + 3; }
                }
            }
        }
    }
    __syncthreads();
    int deg = min(s_cnt, MAXDEG);

    float4 E1 = g_e1[i];

    // ---- phase 2 (fused): 16 slot-warps, exp-free weights + gather + Z ----
    int lane = tid & 31;
    int slot = tid >> 5;                 // 0..15
    const float4* x4 = reinterpret_cast<const float4*>(x);
    float a0x = 0.f, a0y = 0.f, a0z = 0.f, a0w = 0.f;
    float a1x = 0.f, a1y = 0.f, a1z = 0.f, a1w_ = 0.f;
    float z0 = 0.f, z1 = 0.f;
    #pragma unroll 2
    for (int t = slot; t < deg; t += 16) {
        int j = s_list[t];
        float4 E2 = __ldg(&g_e2[j]);                 // warp-uniform broadcast
        float e0 = fmaxf(fmaf(E1.x, E2.x, -1.f), fmaf(E1.y, E2.y, -1.f));
        float e1 = fmaxf(fmaf(E1.z, E2.z, -1.f), fmaf(E1.w, E2.w, -1.f));
        z0 += e0; z1 += e1;                          // warp-uniform accumulation
        float4 xv = __ldg(&x4[(size_t)j * 32 + lane]);
        a0x = fmaf(e0, xv.x, a0x); a1x = fmaf(e1, xv.x, a1x);
        a0y = fmaf(e0, xv.y, a0y); a1y = fmaf(e1, xv.y, a1y);
        a0z = fmaf(e0, xv.z, a0z); a1z = fmaf(e1, xv.z, a1z);
        a0w = fmaf(e0, xv.w, a0w); a1w_ = fmaf(e1, xv.w, a1w_);
    }
    if (lane == 0) { s_z[slot] = z0; s_z[16 + slot] = z1; }  // warp-uniform: NO reduction
    *reinterpret_cast<float4*>(&s_p0[slot][lane * 4]) = make_float4(a0x, a0y, a0z, a0w);
    *reinterpret_cast<float4*>(&s_p1[slot][lane * 4]) = make_float4(a1x, a1y, a1z, a1w_);
    __syncthreads();

    // ---- phase 3: epilogue over 256 threads (head = tid>>7, dim = tid&127) ----
    if (tid < 256) {
        int h = tid >> 7;
        int d = tid & 127;
        float zz = (float)N_NODES;
        #pragma unroll
        for (int s = 0; s < 16; ++s) zz += s_z[h * 16 + s];
        float iz = 1.f / zz;

        float A = 0.f;
        const float (*sp)[132] = h ? s_p1 : s_p0;
        #pragma unroll
        for (int s = 0; s < 16; ++s) A += sp[s][d];
        float v = iz * (A + g_Sx[d]);

        uint32_t hb = (uint32_t)__half_as_ushort(__float2half_rn(v));
        uint32_t hn = __shfl_down_sync(0xffffffffu, hb, 1);
        if ((d & 1) == 0) {
            size_t o = (size_t)i * 128 + (d >> 1) + h * 64;
            g_Ga[o] = hb | (hn << 16);
        }
    }
}

// ============================================================
// Kernel 4: single-pass fp16 m16n8k16 GEMM with ldmatrix fragments.
// BM=64, BN=64, BK=32, 8 chunks, grid=256, 256 threads, 3-stage cp.async.
// ============================================================
__device__ __forceinline__ void mma_fp16(float* d, const uint32_t* a, const uint32_t* b) {
    asm volatile(
        "mma.sync.aligned.m16n8k16.row.col.f32.f16.f16.f32 "
        "{%0,%1,%2,%3},{%4,%5,%6,%7},{%8,%9},{%0,%1,%2,%3};\n"
        : "+f"(d[0]), "+f"(d[1]), "+f"(d[2]), "+f"(d[3])
        : "r"(a[0]), "r"(a[1]), "r"(a[2]), "r"(a[3]), "r"(b[0]), "r"(b[1]));
}
__device__ __forceinline__ void cpa16(uint32_t dst, const uint32_t* src) {
    asm volatile("cp.async.cg.shared.global [%0], [%1], 16;\n" :: "r"(dst), "l"(src));
}
__device__ __forceinline__ void ldsm_x4(uint32_t* r, uint32_t addr) {
    asm volatile("ldmatrix.sync.aligned.m8n8.x4.shared.b16 {%0,%1,%2,%3}, [%4];"
                 : "=r"(r[0]), "=r"(r[1]), "=r"(r[2]), "=r"(r[3]) : "r"(addr));
}

#define A_STAGE (64 * 80)     // 5120 B
#define B_STAGE (64 * 80)     // 5120 B

__global__ void __launch_bounds__(256) gemm_fp16(const float* __restrict__ bias,
                                                 float* __restrict__ out) {
    __shared__ __align__(128) uint8_t sA[3 * A_STAGE];
    __shared__ __align__(128) uint8_t sB[3 * B_STAGE];

    int tid = threadIdx.x;
    int wid = tid >> 5, lane = tid & 31;
    int grp = lane >> 2, thr = lane & 3;
    int wm = wid & 1;                   // m32 block (2)
    int wn = wid >> 1;                  // n16 block (4)
    int row0 = (blockIdx.x >> 1) * 64;
    int ncol0 = (blockIdx.x & 1) * 64;

    uint32_t sAb = smem_u32(sA);
    uint32_t sBb = smem_u32(sB);

    auto issue = [&](int c) {
        int st = c % 3;
        int kp0 = c * 16;                             // 16 kpairs = 32 k per chunk
        int r = tid >> 2, q = tid & 3;                // 64 rows x 4 quads, 1/thread
        cpa16(sAb + st * A_STAGE + r * 80 + q * 16,
              g_Ga + (size_t)(row0 + r) * 128 + kp0 + q * 4);
        cpa16(sBb + st * B_STAGE + r * 80 + q * 16,
              g_Kb + (size_t)(ncol0 + r) * 128 + kp0 + q * 4);
        asm volatile("cp.async.commit_group;\n");
    };

    float acc[2][2][4];
    #pragma unroll
    for (int mi = 0; mi < 2; ++mi)
        #pragma unroll
        for (int ni = 0; ni < 2; ++ni)
            #pragma unroll
            for (int q = 0; q < 4; ++q) acc[mi][ni][q] = 0.f;

    issue(0);
    issue(1);

    #pragma unroll 1
    for (int c = 0; c < 8; ++c) {
        asm volatile("cp.async.wait_group 1;\n" ::: "memory");
        __syncthreads();
        if (c + 2 < 8) issue(c + 2);
        else asm volatile("cp.async.commit_group;\n");

        int st = c % 3;
        uint32_t aB = sAb + st * A_STAGE;
        uint32_t bB = sBb + st * B_STAGE;

        uint32_t afr[2][2][4];
        #pragma unroll
        for (int mi = 0; mi < 2; ++mi)
            #pragma unroll
            for (int s = 0; s < 2; ++s) {
                int r = wm * 32 + mi * 16 + (lane & 15);
                int q = s * 2 + (lane >> 4);
                ldsm_x4(afr[mi][s], aB + r * 80 + q * 16);
            }
        uint32_t bfr[2][4];
        #pragma unroll
        for (int ni = 0; ni < 2; ++ni) {
            int r = wn * 16 + ni * 8 + (lane & 7);
            int q = lane >> 3;
            ldsm_x4(bfr[ni], bB + r * 80 + q * 16);
        }
        #pragma unroll
        for (int s = 0; s < 2; ++s)
            #pragma unroll
            for (int mi = 0; mi < 2; ++mi)
                #pragma unroll
                for (int ni = 0; ni < 2; ++ni)
                    mma_fp16(acc[mi][ni], afr[mi][s], &bfr[ni][2 * s]);
    }

    // epilogue
    #pragma unroll
    for (int mi = 0; mi < 2; ++mi)
        #pragma unroll
        for (int ni = 0; ni < 2; ++ni) {
            int c0 = ncol0 + wn * 16 + ni * 8 + 2 * thr;
            #pragma unroll
            for (int half = 0; half < 2; ++half) {
                int r = row0 + wm * 32 + mi * 16 + grp + half * 8;
                size_t o = (size_t)r * 128 + c0;
                const float2 b0 = *reinterpret_cast<const float2*>(bias + o);
                const float2 b1 = *reinterpret_cast<const float2*>(bias + (size_t)N_NODES * 128 + o);
                float2 res;
                res.x = 0.5f * (acc[mi][ni][half * 2 + 0] + b0.x + b1.x);
                res.y = 0.5f * (acc[mi][ni][half * 2 + 1] + b0.y + b1.y);
                *reinterpret_cast<float2*>(out + o) = res;
            }
        }
}

// ============================================================
extern "C" void kernel_launch(void* const* d_in, const int* in_sizes, int n_in,
                              void* d_out, int out_size) {
    const float* x    = (const float*)d_in[0];
    const float* adj  = (const float*)d_in[1];
    const float* Wmap = (const float*)d_in[2];
    const float* a1w  = (const float*)d_in[3];
    const float* a1b  = (const float*)d_in[4];
    const float* a2w  = (const float*)d_in[5];
    const float* a2b  = (const float*)d_in[6];
    const float* kern = (const float*)d_in[7];
    const float* bias = (const float*)d_in[8];
    float* out = (float*)d_out;

    prep_all<<<129, 256>>>(Wmap, a1w, a2w, kern);
    score_kernel<<<1024, 256>>>(x, a1b, a2b);
    gat_main<<<N_NODES, 512>>>(adj, x);
    gemm_fp16<<<256, 256>>>(bias, out);
}

// round 16
// speedup vs baseline: 1.1200x; 1.1200x over previous
#include <cuda_runtime.h>
#include <cuda_fp16.h>
#include <cstdint>

#define N_NODES 8192
#define F_DIM 128
#define ALPHA 0.3f
#define MAXDEG 512

// ---- device scratch ----
__device__ float    g_v[4 * F_DIM];
__device__ float    g_Sx[F_DIM];
__device__ float2   g_sa1p[N_NODES];
__device__ float2   g_sa2p[N_NODES];
// G as fp16, k-pair packed: [row][128 kpairs] (256 k per row)
__device__ uint32_t g_Ga[(size_t)N_NODES * 128];
// K as fp16, transposed + k-pair packed: [n(128)][128 kpairs]
__device__ uint32_t g_Kb[128 * 128];

__device__ __forceinline__ uint32_t smem_u32(const void* p) {
    uint32_t a;
    asm("{ .reg .u64 t; cvta.to.shared.u64 t, %1; cvt.u32.u64 %0, t; }" : "=r"(a) : "l"(p));
    return a;
}

// ============================================================
// Kernel 1: blocks 0..127 pack K (fp16); block 128 computes v + zeroes Sx
// ============================================================
__global__ void prep_all(const float* __restrict__ Wmap,
                         const float* __restrict__ a1w,
                         const float* __restrict__ a2w,
                         const float* __restrict__ Kw) {
    int t = threadIdx.x;
    if (blockIdx.x < 128) {
        if (t < 128) {
            int n = blockIdx.x;
            int kp = t;
            float v0 = Kw[(size_t)(2 * kp) * 128 + n];
            float v1 = Kw[(size_t)(2 * kp + 1) * 128 + n];
            __half2 h = __floats2half2_rn(v0, v1);
            g_Kb[n * 128 + kp] = *reinterpret_cast<uint32_t*>(&h);
        }
    } else {
        int h = t >> 7, f = t & 127;
        const float* wrow = Wmap + (size_t)(h * F_DIM + f) * 128;
        float s1 = 0.f, s2 = 0.f;
        for (int d = 0; d < 128; ++d) {
            float w = wrow[d];
            s1 = fmaf(w, a1w[h * 128 + d], s1);
            s2 = fmaf(w, a2w[h * 128 + d], s2);
        }
        g_v[h * F_DIM + f] = s1;
        g_v[2 * F_DIM + h * F_DIM + f] = s2;
        if (t < F_DIM) g_Sx[t] = 0.f;
    }
}

// ============================================================
// Kernel 2: per-node scores (packed float2) + fused column sums
// ============================================================
__global__ void __launch_bounds__(256) score_kernel(const float* __restrict__ x,
                                                    const float* __restrict__ a1b,
                                                    const float* __restrict__ a2b) {
    __shared__ float sv[4 * 128];
    __shared__ float s_colp[8][128];
    int tid = threadIdx.x;
    sv[tid] = g_v[tid];
    sv[256 + tid] = g_v[256 + tid];

    int warp = tid >> 5, lane = tid & 31;
    int n = blockIdx.x * 8 + warp;
    const float* xr = x + (size_t)n * F_DIM;
    float x0 = xr[lane], x1 = xr[lane + 32], x2 = xr[lane + 64], x3 = xr[lane + 96];

    s_colp[warp][lane]      = x0;
    s_colp[warp][lane + 32] = x1;
    s_colp[warp][lane + 64] = x2;
    s_colp[warp][lane + 96] = x3;
    __syncthreads();

    float s[4];
    #pragma unroll
    for (int q = 0; q < 4; ++q) {
        const float* v = sv + q * 128;
        float acc = x0 * v[lane] + x1 * v[lane + 32] + x2 * v[lane + 64] + x3 * v[lane + 96];
        #pragma unroll
        for (int o = 16; o > 0; o >>= 1)
            acc += __shfl_down_sync(0xffffffffu, acc, o);
        s[q] = acc;
    }
    if (lane == 0) {
        g_sa1p[n] = make_float2(s[0] + a1b[0], s[1] + a1b[1]);
        g_sa2p[n] = make_float2(s[2] + a2b[0], s[3] + a2b[1]);
    }
    if (tid < 128) {
        float cs = 0.f;
        #pragma unroll
        for (int w = 0; w < 8; ++w) cs += s_colp[w][tid];
        atomicAdd(&g_Sx[tid], cs);
    }
}

// ============================================================
// Kernel 3 (main): R11 structure — adj scan -> fused (e-1) gather
// (unroll 4) -> fp16 pack
//   g = (1/Z) * ( sum_j (e_j - 1) x_j + Sx ),  Z = sum_j (e_j - 1) + N
// ============================================================
__global__ void __launch_bounds__(256) gat_main(const float* __restrict__ adj,
                                                const float* __restrict__ x) {
    __shared__ int   s_list[MAXDEG];
    __shared__ float s_p0[8][132], s_p1[8][132];
    __shared__ float s_z[16];
    __shared__ int   s_cnt;

    int tid = threadIdx.x;
    int i = blockIdx.x;
    if (tid == 0) s_cnt = 0;
    __syncthreads();

    // ---- phase 1: streaming scan; 2 batches of 4, 64B-group OR test ----
    const uint4* arow = reinterpret_cast<const uint4*>(adj + (size_t)i * N_NODES);
    #pragma unroll
    for (int g4 = 0; g4 < 2; ++g4) {
        uint4 a[4];
        #pragma unroll
        for (int it = 0; it < 4; ++it)
            a[it] = __ldcs(&arow[(g4 * 4 + it) * 256 + tid]);
        uint32_t any = (a[0].x | a[0].y | a[0].z | a[0].w)
                     | (a[1].x | a[1].y | a[1].z | a[1].w)
                     | (a[2].x | a[2].y | a[2].z | a[2].w)
                     | (a[3].x | a[3].y | a[3].z | a[3].w);
        if (any != 0u) {
            #pragma unroll
            for (int it = 0; it < 4; ++it) {
                uint4 v = a[it];
                if ((v.x | v.y | v.z | v.w) != 0u) {
                    int jb = ((g4 * 4 + it) * 256 + tid) << 2;
                    if (v.x) { int p = atomicAdd(&s_cnt, 1); if (p < MAXDEG) s_list[p] = jb; }
                    if (v.y) { int p = atomicAdd(&s_cnt, 1); if (p < MAXDEG) s_list[p] = jb + 1; }
                    if (v.z) { int p = atomicAdd(&s_cnt, 1); if (p < MAXDEG) s_list[p] = jb + 2; }
                    if (v.w) { int p = atomicAdd(&s_cnt, 1); if (p < MAXDEG) s_list[p] = jb + 3; }
                }
            }
        }
    }
    __syncthreads();
    int deg = min(s_cnt, MAXDEG);

    float2 sa1 = g_sa1p[i];

    // ---- phase 2 (fused): per-slot-warp (e-1) + weighted gather + Z ----
    int lane = tid & 31;
    int slot = tid >> 5;
    const float4* x4 = reinterpret_cast<const float4*>(x);
    float a0x = 0.f, a0y = 0.f, a0z = 0.f, a0w = 0.f;
    float a1x = 0.f, a1y = 0.f, a1z = 0.f, a1w_ = 0.f;
    float z0 = 0.f, z1 = 0.f;
    #pragma unroll 4
    for (int t = slot; t < deg; t += 8) {
        int j = s_list[t];
        float2 s2 = __ldg(&g_sa2p[j]);               // warp-uniform broadcast
        float w0 = sa1.x + s2.x;  w0 = fmaxf(w0, ALPHA * w0);
        float w1 = sa1.y + s2.y;  w1 = fmaxf(w1, ALPHA * w1);
        float e0 = __expf(w0) - 1.f;
        float e1 = __expf(w1) - 1.f;
        z0 += e0; z1 += e1;                          // warp-uniform accumulation
        float4 xv = __ldg(&x4[(size_t)j * 32 + lane]);
        a0x = fmaf(e0, xv.x, a0x); a1x = fmaf(e1, xv.x, a1x);
        a0y = fmaf(e0, xv.y, a0y); a1y = fmaf(e1, xv.y, a1y);
        a0z = fmaf(e0, xv.z, a0z); a1z = fmaf(e1, xv.z, a1z);
        a0w = fmaf(e0, xv.w, a0w); a1w_ = fmaf(e1, xv.w, a1w_);
    }
    if (lane == 0) { s_z[slot] = z0; s_z[8 + slot] = z1; }   // warp-uniform: NO reduction
    *reinterpret_cast<float4*>(&s_p0[slot][lane * 4]) = make_float4(a0x, a0y, a0z, a0w);
    *reinterpret_cast<float4*>(&s_p1[slot][lane * 4]) = make_float4(a1x, a1y, a1z, a1w_);
    __syncthreads();

    // ---- phase 3: combine + normalize + fp16 kpair pack ----
    if (tid < 128) {
        float zz0 = (float)N_NODES, zz1 = (float)N_NODES;
        #pragma unroll
        for (int s = 0; s < 8; ++s) { zz0 += s_z[s]; zz1 += s_z[8 + s]; }
        float iz0 = 1.f / zz0;
        float iz1 = 1.f / zz1;

        float A0 = 0.f, A1 = 0.f;
        #pragma unroll
        for (int s = 0; s < 8; ++s) { A0 += s_p0[s][tid]; A1 += s_p1[s][tid]; }
        float sx = g_Sx[tid];
        float v0 = iz0 * (A0 + sx);
        float v1 = iz1 * (A1 + sx);

        uint32_t h0 = (uint32_t)__half_as_ushort(__float2half_rn(v0));
        uint32_t h1 = (uint32_t)__half_as_ushort(__float2half_rn(v1));
        uint32_t h0n = __shfl_down_sync(0xffffffffu, h0, 1);
        uint32_t h1n = __shfl_down_sync(0xffffffffu, h1, 1);
        if ((tid & 1) == 0) {
            size_t o = (size_t)i * 128 + (tid >> 1);
            g_Ga[o]      = h0 | (h0n << 16);
            g_Ga[o + 64] = h1 | (h1n << 16);
        }
    }
}

// ============================================================
// Kernel 4: single-pass fp16 m16n8k16 GEMM with ldmatrix fragments.
// BM=64, BN=64, BK=32, 8 chunks, grid=256, 256 threads, 3-stage cp.async.
// ============================================================
__device__ __forceinline__ void mma_fp16(float* d, const uint32_t* a, const uint32_t* b) {
    asm volatile(
        "mma.sync.aligned.m16n8k16.row.col.f32.f16.f16.f32 "
        "{%0,%1,%2,%3},{%4,%5,%6,%7},{%8,%9},{%0,%1,%2,%3};\n"
        : "+f"(d[0]), "+f"(d[1]), "+f"(d[2]), "+f"(d[3])
        : "r"(a[0]), "r"(a[1]), "r"(a[2]), "r"(a[3]), "r"(b[0]), "r"(b[1]));
}
__device__ __forceinline__ void cpa16(uint32_t dst, const uint32_t* src) {
    asm volatile("cp.async.cg.shared.global [%0], [%1], 16;\n" :: "r"(dst), "l"(src));
}
__device__ __forceinline__ void ldsm_x4(uint32_t* r, uint32_t addr) {
    asm volatile("ldmatrix.sync.aligned.m8n8.x4.shared.b16 {%0,%1,%2,%3}, [%4];"
                 : "=r"(r[0]), "=r"(r[1]), "=r"(r[2]), "=r"(r[3]) : "r"(addr));
}

#define A_STAGE (64 * 80)     // 5120 B
#define B_STAGE (64 * 80)     // 5120 B

__global__ void __launch_bounds__(256) gemm_fp16(const float* __restrict__ bias,
                                                 float* __restrict__ out) {
    __shared__ __align__(128) uint8_t sA[3 * A_STAGE];
    __shared__ __align__(128) uint8_t sB[3 * B_STAGE];

    int tid = threadIdx.x;
    int wid = tid >> 5, lane = tid & 31;
    int grp = lane >> 2, thr = lane & 3;
    int wm = wid & 1;                   // m32 block (2)
    int wn = wid >> 1;                  // n16 block (4)
    int row0 = (blockIdx.x >> 1) * 64;
    int ncol0 = (blockIdx.x & 1) * 64;

    uint32_t sAb = smem_u32(sA);
    uint32_t sBb = smem_u32(sB);

    auto issue = [&](int c) {
        int st = c % 3;
        int kp0 = c * 16;                             // 16 kpairs = 32 k per chunk
        int r = tid >> 2, q = tid & 3;                // 64 rows x 4 quads, 1/thread
        cpa16(sAb + st * A_STAGE + r * 80 + q * 16,
              g_Ga + (size_t)(row0 + r) * 128 + kp0 + q * 4);
        cpa16(sBb + st * B_STAGE + r * 80 + q * 16,
              g_Kb + (size_t)(ncol0 + r) * 128 + kp0 + q * 4);
        asm volatile("cp.async.commit_group;\n");
    };

    float acc[2][2][4];
    #pragma unroll
    for (int mi = 0; mi < 2; ++mi)
        #pragma unroll
        for (int ni = 0; ni < 2; ++ni)
            #pragma unroll
            for (int q = 0; q < 4; ++q) acc[mi][ni][q] = 0.f;

    issue(0);
    issue(1);

    #pragma unroll 1
    for (int c = 0; c < 8; ++c) {
        asm volatile("cp.async.wait_group 1;\n" ::: "memory");
        __syncthreads();
        if (c + 2 < 8) issue(c + 2);
        else asm volatile("cp.async.commit_group;\n");

        int st = c % 3;
        uint32_t aB = sAb + st * A_STAGE;
        uint32_t bB = sBb + st * B_STAGE;

        uint32_t afr[2][2][4];
        #pragma unroll
        for (int mi = 0; mi < 2; ++mi)
            #pragma unroll
            for (int s = 0; s < 2; ++s) {
                int r = wm * 32 + mi * 16 + (lane & 15);
                int q = s * 2 + (lane >> 4);
                ldsm_x4(afr[mi][s], aB + r * 80 + q * 16);
            }
        uint32_t bfr[2][4];
        #pragma unroll
        for (int ni = 0; ni < 2; ++ni) {
            int r = wn * 16 + ni * 8 + (lane & 7);
            int q = lane >> 3;
            ldsm_x4(bfr[ni], bB + r * 80 + q * 16);
        }
        #pragma unroll
        for (int s = 0; s < 2; ++s)
            #pragma unroll
            for (int mi = 0; mi < 2; ++mi)
                #pragma unroll
                for (int ni = 0; ni < 2; ++ni)
                    mma_fp16(acc[mi][ni], afr[mi][s], &bfr[ni][2 * s]);
    }

    // epilogue
    #pragma unroll
    for (int mi = 0; mi < 2; ++mi)
        #pragma unroll
        for (int ni = 0; ni < 2; ++ni) {
            int c0 = ncol0 + wn * 16 + ni * 8 + 2 * thr;
            #pragma unroll
            for (int half = 0; half < 2; ++half) {
                int r = row0 + wm * 32 + mi * 16 + grp + half * 8;
                size_t o = (size_t)r * 128 + c0;
                const float2 b0 = *reinterpret_cast<const float2*>(bias + o);
                const float2 b1 = *reinterpret_cast<const float2*>(bias + (size_t)N_NODES * 128 + o);
                float2 res;
                res.x = 0.5f * (acc[mi][ni][half * 2 + 0] + b0.x + b1.x);
                res.y = 0.5f * (acc[mi][ni][half * 2 + 1] + b0.y + b1.y);
                *reinterpret_cast<float2*>(out + o) = res;
            }
        }
}

// ============================================================
extern "C" void kernel_launch(void* const* d_in, const int* in_sizes, int n_in,
                              void* d_out, int out_size) {
    const float* x    = (const float*)d_in[0];
    const float* adj  = (const float*)d_in[1];
    const float* Wmap = (const float*)d_in[2];
    const float* a1w  = (const float*)d_in[3];
    const float* a1b  = (const float*)d_in[4];
    const float* a2w  = (const float*)d_in[5];
    const float* a2b  = (const float*)d_in[6];
    const float* kern = (const float*)d_in[7];
    const float* bias = (const float*)d_in[8];
    float* out = (float*)d_out;

    prep_all<<<129, 256>>>(Wmap, a1w, a2w, kern);
    score_kernel<<<1024, 256>>>(x, a1b, a2b);
    gat_main<<<N_NODES, 256>>>(adj, x);
    gemm_fp16<<<256, 256>>>(bias, out);
}